// round 13
// baseline (speedup 1.0000x reference)
#include <cuda_runtime.h>
#include <cuda_bf16.h>
#include <cuda_fp16.h>
#include <cstdint>

#define B_ROWS 8192
#define INP    1024
#define HID    1024
#define MEMSZ  256
#define KTOT   2304   // INP + HID + MEMSZ
#define HM     1280   // HID + MEMSZ (gemm2 K, fp16)
#define NU     136
#define NUP    144

// ------------------- device scratch (static: no allocation) -------------------
__device__ __align__(16) __half g_A16[(size_t)B_ROWS * KTOT];  // gemm1 A fp16
__device__ __align__(16) __half g_W16[(size_t)HID * KTOT];     // gemm1 W fp16
__device__ __align__(16) __half g_A216[(size_t)B_ROWS * HM];   // gemm2 A fp16 [h|mem]
__device__ __align__(16) __half g_W216[(size_t)NUP * HM];      // gemm2 W fp16

// ============================ helpers ============================
__device__ __forceinline__ uint32_t smem_u32(const void* p) {
    uint32_t a;
    asm("{ .reg .u64 t; cvta.to.shared.u64 t, %1; cvt.u32.u64 %0, t; }" : "=r"(a) : "l"(p));
    return a;
}
__device__ __forceinline__ uint32_t swz(uint32_t rowbase128, uint32_t q) {
    return rowbase128 + (q ^ ((rowbase128 >> 3) & 0x70u));
}

#define CP_ASYNC16(saddr, gptr) \
    asm volatile("cp.async.cg.shared.global [%0], [%1], 16;" :: "r"(saddr), "l"(gptr))
#define CP_COMMIT() asm volatile("cp.async.commit_group;" ::: "memory")
#define CP_WAIT0()  asm volatile("cp.async.wait_group 0;" ::: "memory")
#define CP_WAIT1()  asm volatile("cp.async.wait_group 1;" ::: "memory")

__device__ __forceinline__ void ldsm_x4(uint32_t* r, uint32_t addr) {
    asm volatile("ldmatrix.sync.aligned.m8n8.x4.shared.b16 {%0,%1,%2,%3}, [%4];"
                 : "=r"(r[0]), "=r"(r[1]), "=r"(r[2]), "=r"(r[3]) : "r"(addr));
}
__device__ __forceinline__ void ldsm_x2(uint32_t* r, uint32_t addr) {
    asm volatile("ldmatrix.sync.aligned.m8n8.x2.shared.b16 {%0,%1}, [%2];"
                 : "=r"(r[0]), "=r"(r[1]) : "r"(addr));
}
__device__ __forceinline__ void mma_f16(float* d, const uint32_t* a,
                                        uint32_t b0, uint32_t b1) {
    asm volatile("mma.sync.aligned.m16n8k16.row.col.f32.f16.f16.f32 "
                 "{%0,%1,%2,%3}, {%4,%5,%6,%7}, {%8,%9}, {%0,%1,%2,%3};"
                 : "+f"(d[0]), "+f"(d[1]), "+f"(d[2]), "+f"(d[3])
                 : "r"(a[0]), "r"(a[1]), "r"(a[2]), "r"(a[3]), "r"(b0), "r"(b1));
}

// ============================================================================
// Fused conversion kernel (one launch): block ranges -> A, W, W2.
// ============================================================================
struct hf4 { __half2 a, b; };

#define NBLK_A  (B_ROWS * (KTOT / 4) / 256)           // 18432
#define NBLK_W  (HID * (KTOT / 4) / 256)              // 2304
#define NBLK_W2 ((NUP * (HM / 4) + 255) / 256)        // 180

__device__ __forceinline__ const float* u_wrow(int n, const float* Wa, const float* Wb,
                                               const float* Wva, const float* Wvb)
{
    if (n < 4)  return Wa  + (size_t)n * HM;
    if (n < 8)  return Wb  + (size_t)(n - 4) * HM;
    if (n < 72) return Wva + (size_t)(n - 8) * HM;
    return Wvb + (size_t)(n - 72) * HM;
}
__device__ __forceinline__ float u_bias(int n, const float* ba, const float* bb,
                                        const float* bva, const float* bvb)
{
    if (n < 4)  return ba[n];
    if (n < 8)  return bb[n - 4];
    if (n < 72) return bva[n - 8];
    return bvb[n - 72];
}

__global__ void conv_all(const float* __restrict__ x, const float* __restrict__ h0,
                         const float* __restrict__ mem, const float* __restrict__ Wh,
                         const float* __restrict__ Wa, const float* __restrict__ Wb,
                         const float* __restrict__ Wva, const float* __restrict__ Wvb)
{
    const int blk = blockIdx.x;
    if (blk < NBLK_A) {
        const int gid = blk * 256 + threadIdx.x;
        const int row = gid / (KTOT / 4);
        const int k   = (gid % (KTOT / 4)) * 4;
        float4 v;
        if (k < INP)            v = *(const float4*)(x   + (size_t)row * INP + k);
        else if (k < INP + HID) v = *(const float4*)(h0  + (size_t)row * HID + (k - INP));
        else                    v = *(const float4*)(mem + (size_t)row * MEMSZ + (k - INP - HID));

        hf4 a16;
        a16.a = __half2(__float2half_rn(v.x), __float2half_rn(v.y));
        a16.b = __half2(__float2half_rn(v.z), __float2half_rn(v.w));
        *(hf4*)(g_A16 + (size_t)row * KTOT + k) = a16;

        if (k >= INP + HID) {
            const int km = k - (INP + HID);
            *(hf4*)(g_A216 + (size_t)row * HM + HID + km) = a16;
        }
    } else if (blk < NBLK_A + NBLK_W) {
        const int gid = (blk - NBLK_A) * 256 + threadIdx.x;
        const int row = gid / (KTOT / 4);
        const int k   = (gid % (KTOT / 4)) * 4;
        const float4 v = *(const float4*)(Wh + (size_t)row * KTOT + k);
        hf4 w;
        w.a = __half2(__float2half_rn(v.x), __float2half_rn(v.y));
        w.b = __half2(__float2half_rn(v.z), __float2half_rn(v.w));
        *(hf4*)(g_W16 + (size_t)row * KTOT + k) = w;
    } else {
        const int gid = (blk - NBLK_A - NBLK_W) * 256 + threadIdx.x;
        if (gid >= NUP * (HM / 4)) return;
        const int n = gid / (HM / 4);
        const int k = (gid % (HM / 4)) * 4;
        float4 v = make_float4(0.f, 0.f, 0.f, 0.f);
        if (n < NU) v = *(const float4*)(u_wrow(n, Wa, Wb, Wva, Wvb) + k);
        hf4 w;
        w.a = __half2(__float2half_rn(v.x), __float2half_rn(v.y));
        w.b = __half2(__float2half_rn(v.z), __float2half_rn(v.w));
        *(hf4*)(g_W216 + (size_t)n * HM + k) = w;
    }
}

// ============================================================================
// GEMM1: pure fp16. h = relu(A @ W^T + b).
// CTA 128x128, 128 threads (4 warps, each 64x64), **3 CTAs/SM** via 2-stage
// pipeline (64KB smem). 12 warps/SM = 3/SMSP hides ldsm + barrier latency.
// Per chunk: wait_group(0); sync; issue load(kc+1); compute(kc).
// ============================================================================
#define G1_TM 128
#define G1_TN 128
#define G1_NC 36
#define G1_A   0
#define G1_B   16384
#define G1_STG 32768
#define G1_SMEM (2 * G1_STG)   // 65536

__global__ __launch_bounds__(128, 3)
void gemm1_mma(const float* __restrict__ bh, float* __restrict__ hout)
{
    extern __shared__ __align__(1024) unsigned char smem[];
    const uint32_t sbase = smem_u32(smem);
    const int tid = threadIdx.x;
    const int wid = tid >> 5;
    const int lid = tid & 31;
    const int N0 = blockIdx.x * G1_TN;
    const int M0 = blockIdx.y * G1_TM;

    // ---------- producer addressing ----------
    const char* pA[8];  uint32_t sAo[8];
    const char* pB[8];
#pragma unroll
    for (int r = 0; r < 8; r++) {
        const int idx = tid + 128 * r, row = idx >> 3, sl = idx & 7;
        pA[r]  = (const char*)g_A16 + (size_t)(M0 + row) * (KTOT * 2) + sl * 16;
        pB[r]  = (const char*)g_W16 + (size_t)(N0 + row) * (KTOT * 2) + sl * 16;
        sAo[r] = swz((uint32_t)row * 128, (uint32_t)sl * 16);
    }

    auto issue_load = [&](int kc, int stage) {
        const uint32_t st = sbase + stage * G1_STG;
        const uint32_t cb = (uint32_t)kc * 128;
#pragma unroll
        for (int r = 0; r < 8; r++) {
            CP_ASYNC16(st + G1_A + sAo[r], pA[r] + cb);
            CP_ASYNC16(st + G1_B + sAo[r], pB[r] + cb);
        }
        CP_COMMIT();
    };

    // ---------- consumer addressing: warp 64x64 ----------
    const int wm = (wid & 1) * 64;
    const int wn = (wid >> 1) * 64;
    const uint32_t arow128 = (uint32_t)(wm + (lid & 15)) * 128;
    const uint32_t aq      = (uint32_t)((lid >> 4) * 16);
    const uint32_t brow128 = (uint32_t)(wn + (lid & 7) + ((lid >> 4) & 1) * 8) * 128;
    const uint32_t bq      = (uint32_t)(((lid >> 3) & 1) * 16);

    float acc[4][8][4];
#pragma unroll
    for (int i = 0; i < 4; i++)
#pragma unroll
        for (int j = 0; j < 8; j++)
#pragma unroll
            for (int q = 0; q < 4; q++) acc[i][j][q] = 0.f;

    issue_load(0, 0);

#pragma unroll 1
    for (int kc = 0; kc < G1_NC; kc++) {
        CP_WAIT0();          // load(kc) complete
        __syncthreads();     // all warps done reading stage (kc+1)%2 from chunk kc-1
        if (kc + 1 < G1_NC) issue_load(kc + 1, (kc + 1) & 1);

        const uint32_t st = sbase + (kc & 1) * G1_STG;
#pragma unroll
        for (int kk = 0; kk < 4; kk++) {
            const uint32_t kb = (uint32_t)kk * 32;
            uint32_t A[4][4], B[4][4];
#pragma unroll
            for (int mt = 0; mt < 4; mt++)
                ldsm_x4(A[mt], st + G1_A + swz(arow128 + mt * 16 * 128, kb + aq));
#pragma unroll
            for (int nt = 0; nt < 4; nt++)
                ldsm_x4(B[nt], st + G1_B + swz(brow128 + nt * 16 * 128, kb + bq));
#pragma unroll
            for (int mt = 0; mt < 4; mt++)
#pragma unroll
                for (int nt = 0; nt < 4; nt++) {
                    mma_f16(acc[mt][2 * nt],     A[mt], B[nt][0], B[nt][1]);
                    mma_f16(acc[mt][2 * nt + 1], A[mt], B[nt][2], B[nt][3]);
                }
        }
    }

    // ---------- epilogue: bias + relu; fp32 h + fp16 into g_A216 ----------
#pragma unroll
    for (int mt = 0; mt < 4; mt++) {
        const int m = M0 + wm + mt * 16 + (lid >> 2);
#pragma unroll
        for (int nt = 0; nt < 8; nt++) {
            const int n = N0 + wn + nt * 8 + (lid & 3) * 2;
            const float2 bv = *(const float2*)(bh + n);
            float2 v0, v1;
            v0.x = acc[mt][nt][0] + bv.x; v0.y = acc[mt][nt][1] + bv.y;
            v1.x = acc[mt][nt][2] + bv.x; v1.y = acc[mt][nt][3] + bv.y;
            v0.x = v0.x > 0.f ? v0.x : 0.f; v0.y = v0.y > 0.f ? v0.y : 0.f;
            v1.x = v1.x > 0.f ? v1.x : 0.f; v1.y = v1.y > 0.f ? v1.y : 0.f;
            *(float2*)(hout + (size_t)m * HID + n)       = v0;
            *(float2*)(hout + (size_t)(m + 8) * HID + n) = v1;
            *(__half2*)(g_A216 + (size_t)m * HM + n) =
                __half2(__float2half_rn(v0.x), __float2half_rn(v0.y));
            *(__half2*)(g_A216 + (size_t)(m + 8) * HM + n) =
                __half2(__float2half_rn(v1.x), __float2half_rn(v1.y));
        }
    }
}

// ============================================================================
// GEMM2: single fp16 product + fused finish (round-12 version, unchanged).
// ============================================================================
#define NSTAGE 3
#define G2_TM 64
#define G2_NCHUNK 20
#define G2_SA (G2_TM * 128)     // 8192
#define G2_SB (NUP * 128)       // 18432
#define G2_STG (G2_SA + G2_SB)  // 26624
#define G2_SMEM (3 * G2_STG)    // 79872

__global__ __launch_bounds__(256, 1)
void gemm2_mma(const float* __restrict__ mem,
               const float* __restrict__ ba, const float* __restrict__ bb,
               const float* __restrict__ bva, const float* __restrict__ bvb,
               float* __restrict__ mem_new)
{
    extern __shared__ __align__(1024) unsigned char smem[];
    const uint32_t sbase = smem_u32(smem);
    const int tid = threadIdx.x;
    const int wid = tid >> 5;
    const int lid = tid & 31;
    const int M0 = blockIdx.x * G2_TM;

    const int prow = tid >> 3;
    const int pc   = tid & 7;
    const char* Ag = (const char*)g_A216 + (size_t)(M0 + prow) * (HM * 2) + pc * 16;
    const uint32_t sAoff = swz((uint32_t)prow * 128, (uint32_t)pc * 16);

    auto issue_load = [&](int kc, int stage) {
        const uint32_t cb = (uint32_t)kc * 128;
        const uint32_t sa  = sbase + stage * G2_STG;
        const uint32_t sbB = sa + G2_SA;
#pragma unroll
        for (int r = 0; r < 2; r++)
            CP_ASYNC16(sa + sAoff + r * 4096, Ag + cb + (size_t)r * (32 * HM * 2));
#pragma unroll
        for (int r = 0; r < 5; r++) {
            const int idx = tid + 256 * r;
            if (idx < NUP * 8) {
                const int row = idx >> 3, c = idx & 7;
                CP_ASYNC16(sbB + swz((uint32_t)row * 128, (uint32_t)c * 16),
                           (const char*)g_W216 + (size_t)row * (HM * 2) + c * 16 + cb);
            }
        }
        CP_COMMIT();
    };

    const int wm = (wid & 3) * 16;
    const int wn = (wid >> 2) * 72;
    const uint32_t arow128 = (uint32_t)(wm + (lid & 15)) * 128;
    const uint32_t aq      = (uint32_t)((lid >> 4) * 16);
    const uint32_t brow128 = (uint32_t)((lid & 7) + ((lid >> 4) & 1) * 8) * 128;
    const uint32_t bq      = (uint32_t)(((lid >> 3) & 1) * 16);
    const uint32_t brow2   = (uint32_t)(lid & 7) * 128;

    float acc[9][4];
#pragma unroll
    for (int j = 0; j < 9; j++)
#pragma unroll
        for (int q = 0; q < 4; q++) acc[j][q] = 0.f;

    issue_load(0, 0);
    issue_load(1, 1);

#pragma unroll 1
    for (int kc = 0; kc < G2_NCHUNK; kc++) {
        CP_WAIT1();
        __syncthreads();
        if (kc + 2 < G2_NCHUNK) issue_load(kc + 2, (kc + 2) % NSTAGE);
        else CP_COMMIT();

        const uint32_t sa  = sbase + (kc % NSTAGE) * G2_STG;
        const uint32_t sbB = sa + G2_SA;
#pragma unroll
        for (int kk = 0; kk < 4; kk++) {
            const uint32_t kb = (uint32_t)kk * 32;
            uint32_t A[4];
            ldsm_x4(A, sa + swz(arow128, kb + aq));
            uint32_t Bf[4][4], Bt[2];
#pragma unroll
            for (int nt = 0; nt < 4; nt++)
                ldsm_x4(Bf[nt], sbB + swz(brow128 + (wn + nt * 16) * 128, kb + bq));
            ldsm_x2(Bt, sbB + swz(brow2 + (wn + 64) * 128, kb + bq));
#pragma unroll
            for (int nt = 0; nt < 4; nt++) {
                mma_f16(acc[2 * nt],     A, Bf[nt][0], Bf[nt][1]);
                mma_f16(acc[2 * nt + 1], A, Bf[nt][2], Bf[nt][3]);
            }
            mma_f16(acc[8], A, Bt[0], Bt[1]);
        }
    }

    __syncthreads();
    float* su = (float*)smem;                      // [64][144]
    float* Pa = (float*)(smem + 64 * NUP * 4);     // [64][8]
    float* Pb = Pa + 64 * 8;
    {
        const int r0 = wm + (lid >> 2);
        const int r1 = r0 + 8;
#pragma unroll
        for (int nt = 0; nt < 9; nt++) {
            const int n = wn + nt * 8 + (lid & 3) * 2;
            float b0 = 0.f, b1 = 0.f;
            if (n < NU)     b0 = u_bias(n,     ba, bb, bva, bvb);
            if (n + 1 < NU) b1 = u_bias(n + 1, ba, bb, bva, bvb);
            su[r0 * NUP + n]     = acc[nt][0] + b0;
            su[r0 * NUP + n + 1] = acc[nt][1] + b1;
            su[r1 * NUP + n]     = acc[nt][2] + b0;
            su[r1 * NUP + n + 1] = acc[nt][3] + b1;
        }
    }
    __syncthreads();

    if (tid < 64) {
        const float* u   = su + tid * NUP;
        const float* al  = u;
        const float* be  = u + 4;
        const float* u0a = u + 8;
        const float* u1a = u + 40;
        const float* u0b = u + 72;
        const float* u1b = u + 104;

        float S1a = 0.f, S1b = 0.f;
#pragma unroll
        for (int j = 0; j < 32; j++) {
            const float xa = u1a[j], xa2 = xa * xa;
            const float xb = u1b[j], xb2 = xb * xb;
            S1a += xa2 * xa2 * fabsf(xa);
            S1b += xb2 * xb2 * fabsf(xb);
        }
        float ca[4], cb[4];
#pragma unroll
        for (int k = 0; k < 4; k++) {
            float S0a = 0.f, S0b = 0.f;
#pragma unroll
            for (int i = 0; i < 8; i++) {
                const float xa = u0a[8 * k + i], xa2 = xa * xa;
                const float xb = u0b[8 * k + i], xb2 = xb * xb;
                S0a += xa2 * xa2 * fabsf(xa);
                S0b += xb2 * xb2 * fabsf(xb);
            }
            const float na = fmaxf(exp2f(0.2f * log2f(S0a * S1a)), 1e-12f);
            const float nb = fmaxf(exp2f(0.2f * log2f(S0b * S1b)), 1e-12f);
            ca[k] = al[k] / na;
            cb[k] = be[k] / nb;
        }
#pragma unroll
        for (int ii = 0; ii < 8; ii++) {
            float pa = 0.f, pb = 0.f;
#pragma unroll
            for (int k = 0; k < 4; k++) {
                pa += ca[k] * u0a[8 * k + ii];
                pb += cb[k] * u0b[8 * k + ii];
            }
            Pa[tid * 8 + ii] = pa;
            Pb[tid * 8 + ii] = pb;
        }
    }
    __syncthreads();

#pragma unroll
    for (int e = 0; e < 64; e++) {
        const int idx = tid + e * 256;
        const int m = idx >> 8;
        const int c = idx & 255;
        const int ii = c >> 5;
        const int j  = c & 31;
        const float* u = su + m * NUP;
        mem_new[(size_t)(M0 + m) * MEMSZ + c] =
            mem[(size_t)(M0 + m) * MEMSZ + c] +
            0.25f * (u[40 + j] * Pa[m * 8 + ii] - u[104 + j] * Pb[m * 8 + ii]);
    }
}

// ============================================================================
// Launch
// ============================================================================
extern "C" void kernel_launch(void* const* d_in, const int* in_sizes, int n_in,
                              void* d_out, int out_size)
{
    const float* x   = (const float*)d_in[0];
    const float* h0  = (const float*)d_in[1];
    const float* mem = (const float*)d_in[2];
    const float* Wh  = (const float*)d_in[3];
    const float* bh  = (const float*)d_in[4];
    const float* Wa  = (const float*)d_in[5];
    const float* ba  = (const float*)d_in[6];
    const float* Wb  = (const float*)d_in[7];
    const float* bb  = (const float*)d_in[8];
    const float* Wva = (const float*)d_in[9];
    const float* bva = (const float*)d_in[10];
    const float* Wvb = (const float*)d_in[11];
    const float* bvb = (const float*)d_in[12];

    float* out     = (float*)d_out;
    float* mem_new = out;                              // [B, 256]
    float* h       = out + (size_t)B_ROWS * MEMSZ;     // [B, 1024]

    cudaFuncSetAttribute(gemm1_mma, cudaFuncAttributeMaxDynamicSharedMemorySize, G1_SMEM);
    cudaFuncSetAttribute(gemm2_mma, cudaFuncAttributeMaxDynamicSharedMemorySize, G2_SMEM);

    conv_all<<<NBLK_A + NBLK_W + NBLK_W2, 256>>>(x, h0, mem, Wh, Wa, Wb, Wva, Wvb);
    gemm1_mma<<<dim3(HID / G1_TN, B_ROWS / G1_TM), 128, G1_SMEM>>>(bh, h);
    gemm2_mma<<<B_ROWS / G2_TM, 256, G2_SMEM>>>(mem, ba, bb, bva, bvb, mem_new);
}

// round 14
// speedup vs baseline: 1.2570x; 1.2570x over previous
#include <cuda_runtime.h>
#include <cuda_bf16.h>
#include <cuda_fp16.h>
#include <cstdint>

#define B_ROWS 8192
#define INP    1024
#define HID    1024
#define MEMSZ  256
#define KTOT   2304   // INP + HID + MEMSZ
#define HM     1280   // HID + MEMSZ (gemm2 K, fp16)
#define NU     136
#define NUP    144

// ------------------- device scratch (static: no allocation) -------------------
__device__ __align__(16) __half g_A16[(size_t)B_ROWS * KTOT];  // gemm1 A fp16
__device__ __align__(16) __half g_W16[(size_t)HID * KTOT];     // gemm1 W fp16
__device__ __align__(16) __half g_A216[(size_t)B_ROWS * HM];   // gemm2 A fp16 [h|mem]
__device__ __align__(16) __half g_W216[(size_t)NUP * HM];      // gemm2 W fp16

// ============================ helpers ============================
__device__ __forceinline__ uint32_t smem_u32(const void* p) {
    uint32_t a;
    asm("{ .reg .u64 t; cvta.to.shared.u64 t, %1; cvt.u32.u64 %0, t; }" : "=r"(a) : "l"(p));
    return a;
}
__device__ __forceinline__ uint32_t swz(uint32_t rowbase128, uint32_t q) {
    return rowbase128 + (q ^ ((rowbase128 >> 3) & 0x70u));
}

#define CP_ASYNC16(saddr, gptr) \
    asm volatile("cp.async.cg.shared.global [%0], [%1], 16;" :: "r"(saddr), "l"(gptr))
#define CP_COMMIT() asm volatile("cp.async.commit_group;" ::: "memory")
#define CP_WAIT1()  asm volatile("cp.async.wait_group 1;" ::: "memory")

__device__ __forceinline__ void ldsm_x4(uint32_t* r, uint32_t addr) {
    asm volatile("ldmatrix.sync.aligned.m8n8.x4.shared.b16 {%0,%1,%2,%3}, [%4];"
                 : "=r"(r[0]), "=r"(r[1]), "=r"(r[2]), "=r"(r[3]) : "r"(addr));
}
__device__ __forceinline__ void ldsm_x2(uint32_t* r, uint32_t addr) {
    asm volatile("ldmatrix.sync.aligned.m8n8.x2.shared.b16 {%0,%1}, [%2];"
                 : "=r"(r[0]), "=r"(r[1]) : "r"(addr));
}
__device__ __forceinline__ void mma_f16(float* d, const uint32_t* a,
                                        uint32_t b0, uint32_t b1) {
    asm volatile("mma.sync.aligned.m16n8k16.row.col.f32.f16.f16.f32 "
                 "{%0,%1,%2,%3}, {%4,%5,%6,%7}, {%8,%9}, {%0,%1,%2,%3};"
                 : "+f"(d[0]), "+f"(d[1]), "+f"(d[2]), "+f"(d[3])
                 : "r"(a[0]), "r"(a[1]), "r"(a[2]), "r"(a[3]), "r"(b0), "r"(b1));
}

// ============================================================================
// Fused conversion kernel: 8 elements per thread (2 x float4) for MLP.
// ============================================================================
struct hf4 { __half2 a, b; };
struct hf8 { __half2 a, b, c, d; };

#define NBLK_A  (B_ROWS * (KTOT / 8) / 256)           // 9216
#define NBLK_W  (HID * (KTOT / 8) / 256)              // 1152
#define NBLK_W2 ((NUP * (HM / 8) + 255) / 256)        // 90

__device__ __forceinline__ const float* u_wrow(int n, const float* Wa, const float* Wb,
                                               const float* Wva, const float* Wvb)
{
    if (n < 4)  return Wa  + (size_t)n * HM;
    if (n < 8)  return Wb  + (size_t)(n - 4) * HM;
    if (n < 72) return Wva + (size_t)(n - 8) * HM;
    return Wvb + (size_t)(n - 72) * HM;
}
__device__ __forceinline__ float u_bias(int n, const float* ba, const float* bb,
                                        const float* bva, const float* bvb)
{
    if (n < 4)  return ba[n];
    if (n < 8)  return bb[n - 4];
    if (n < 72) return bva[n - 8];
    return bvb[n - 72];
}

__device__ __forceinline__ hf8 cvt8(const float4 v0, const float4 v1) {
    hf8 r;
    r.a = __half2(__float2half_rn(v0.x), __float2half_rn(v0.y));
    r.b = __half2(__float2half_rn(v0.z), __float2half_rn(v0.w));
    r.c = __half2(__float2half_rn(v1.x), __float2half_rn(v1.y));
    r.d = __half2(__float2half_rn(v1.z), __float2half_rn(v1.w));
    return r;
}

__global__ void conv_all(const float* __restrict__ x, const float* __restrict__ h0,
                         const float* __restrict__ mem, const float* __restrict__ Wh,
                         const float* __restrict__ Wa, const float* __restrict__ Wb,
                         const float* __restrict__ Wva, const float* __restrict__ Wvb)
{
    const int blk = blockIdx.x;
    if (blk < NBLK_A) {
        const int gid = blk * 256 + threadIdx.x;
        const int row = gid / (KTOT / 8);
        const int k   = (gid % (KTOT / 8)) * 8;
        const float* src;
        if (k < INP)            src = x   + (size_t)row * INP + k;
        else if (k < INP + HID) src = h0  + (size_t)row * HID + (k - INP);
        else                    src = mem + (size_t)row * MEMSZ + (k - INP - HID);
        const float4 v0 = *(const float4*)src;
        const float4 v1 = *(const float4*)(src + 4);
        const hf8 a16 = cvt8(v0, v1);
        *(hf8*)(g_A16 + (size_t)row * KTOT + k) = a16;
        if (k >= INP + HID)
            *(hf8*)(g_A216 + (size_t)row * HM + HID + (k - INP - HID)) = a16;
    } else if (blk < NBLK_A + NBLK_W) {
        const int gid = (blk - NBLK_A) * 256 + threadIdx.x;
        const int row = gid / (KTOT / 8);
        const int k   = (gid % (KTOT / 8)) * 8;
        const float* src = Wh + (size_t)row * KTOT + k;
        const float4 v0 = *(const float4*)src;
        const float4 v1 = *(const float4*)(src + 4);
        *(hf8*)(g_W16 + (size_t)row * KTOT + k) = cvt8(v0, v1);
    } else {
        const int gid = (blk - NBLK_A - NBLK_W) * 256 + threadIdx.x;
        if (gid >= NUP * (HM / 8)) return;
        const int n = gid / (HM / 8);
        const int k = (gid % (HM / 8)) * 8;
        float4 v0 = make_float4(0.f, 0.f, 0.f, 0.f);
        float4 v1 = v0;
        if (n < NU) {
            const float* src = u_wrow(n, Wa, Wb, Wva, Wvb) + k;
            v0 = *(const float4*)src;
            v1 = *(const float4*)(src + 4);
        }
        *(hf8*)(g_W216 + (size_t)n * HM + k) = cvt8(v0, v1);
    }
}

// ============================================================================
// GEMM1: pure fp16 (proven round-12 config, verbatim). h = relu(A @ W^T + b).
// CTA 128x128, 128 threads (4 warps, each 64x64), 2 CTAs/SM.
// 3-stage smem pipeline + register double-buffered fragments.
// ============================================================================
#define G1_TM 128
#define G1_TN 128
#define G1_NC 36
#define G1_A   0
#define G1_B   16384
#define G1_STG 32768
#define G1_SMEM (3 * G1_STG)   // 98304

__global__ __launch_bounds__(128, 2)
void gemm1_mma(const float* __restrict__ bh, float* __restrict__ hout)
{
    extern __shared__ __align__(1024) unsigned char smem[];
    const uint32_t sbase = smem_u32(smem);
    const int tid = threadIdx.x;
    const int wid = tid >> 5;
    const int lid = tid & 31;
    const int N0 = blockIdx.x * G1_TN;
    const int M0 = blockIdx.y * G1_TM;

    const char* pA[8];  uint32_t sAo[8];
    const char* pB[8];
#pragma unroll
    for (int r = 0; r < 8; r++) {
        const int idx = tid + 128 * r, row = idx >> 3, sl = idx & 7;
        pA[r]  = (const char*)g_A16 + (size_t)(M0 + row) * (KTOT * 2) + sl * 16;
        pB[r]  = (const char*)g_W16 + (size_t)(N0 + row) * (KTOT * 2) + sl * 16;
        sAo[r] = swz((uint32_t)row * 128, (uint32_t)sl * 16);
    }

    auto issue_load = [&](int kc, int stage) {
        const uint32_t st = sbase + stage * G1_STG;
        const uint32_t cb = (uint32_t)kc * 128;
#pragma unroll
        for (int r = 0; r < 8; r++) {
            CP_ASYNC16(st + G1_A + sAo[r], pA[r] + cb);
            CP_ASYNC16(st + G1_B + sAo[r], pB[r] + cb);
        }
        CP_COMMIT();
    };

    const int wm = (wid & 1) * 64;
    const int wn = (wid >> 1) * 64;
    const uint32_t arow128 = (uint32_t)(wm + (lid & 15)) * 128;
    const uint32_t aq      = (uint32_t)((lid >> 4) * 16);
    const uint32_t brow128 = (uint32_t)(wn + (lid & 7) + ((lid >> 4) & 1) * 8) * 128;
    const uint32_t bq      = (uint32_t)(((lid >> 3) & 1) * 16);

    float acc[4][8][4];
#pragma unroll
    for (int i = 0; i < 4; i++)
#pragma unroll
        for (int j = 0; j < 8; j++)
#pragma unroll
            for (int q = 0; q < 4; q++) acc[i][j][q] = 0.f;

    issue_load(0, 0);
    issue_load(1, 1);

    uint32_t Af[2][4][4], Bf[2][4][4];

#pragma unroll 1
    for (int kc = 0; kc < G1_NC; kc++) {
        CP_WAIT1();
        __syncthreads();

        const uint32_t st = sbase + (kc % 3) * G1_STG;
#pragma unroll
        for (int mt = 0; mt < 4; mt++)
            ldsm_x4(Af[0][mt], st + G1_A + swz(arow128 + mt * 16 * 128, aq));
#pragma unroll
        for (int nt = 0; nt < 4; nt++)
            ldsm_x4(Bf[0][nt], st + G1_B + swz(brow128 + nt * 16 * 128, bq));

        if (kc + 2 < G1_NC) issue_load(kc + 2, (kc + 2) % 3);
        else CP_COMMIT();

#pragma unroll
        for (int kk = 0; kk < 4; kk++) {
            const int cur = kk & 1, nxt = cur ^ 1;
            if (kk < 3) {
                const uint32_t kb = (uint32_t)(kk + 1) * 32;
#pragma unroll
                for (int mt = 0; mt < 4; mt++)
                    ldsm_x4(Af[nxt][mt], st + G1_A + swz(arow128 + mt * 16 * 128, kb + aq));
#pragma unroll
                for (int nt = 0; nt < 4; nt++)
                    ldsm_x4(Bf[nxt][nt], st + G1_B + swz(brow128 + nt * 16 * 128, kb + bq));
            }
#pragma unroll
            for (int mt = 0; mt < 4; mt++)
#pragma unroll
                for (int nt = 0; nt < 4; nt++) {
                    mma_f16(acc[mt][2 * nt],     Af[cur][mt], Bf[cur][nt][0], Bf[cur][nt][1]);
                    mma_f16(acc[mt][2 * nt + 1], Af[cur][mt], Bf[cur][nt][2], Bf[cur][nt][3]);
                }
        }
    }

#pragma unroll
    for (int mt = 0; mt < 4; mt++) {
        const int m = M0 + wm + mt * 16 + (lid >> 2);
#pragma unroll
        for (int nt = 0; nt < 8; nt++) {
            const int n = N0 + wn + nt * 8 + (lid & 3) * 2;
            const float2 bv = *(const float2*)(bh + n);
            float2 v0, v1;
            v0.x = acc[mt][nt][0] + bv.x; v0.y = acc[mt][nt][1] + bv.y;
            v1.x = acc[mt][nt][2] + bv.x; v1.y = acc[mt][nt][3] + bv.y;
            v0.x = v0.x > 0.f ? v0.x : 0.f; v0.y = v0.y > 0.f ? v0.y : 0.f;
            v1.x = v1.x > 0.f ? v1.x : 0.f; v1.y = v1.y > 0.f ? v1.y : 0.f;
            *(float2*)(hout + (size_t)m * HID + n)       = v0;
            *(float2*)(hout + (size_t)(m + 8) * HID + n) = v1;
            *(__half2*)(g_A216 + (size_t)m * HM + n) =
                __half2(__float2half_rn(v0.x), __float2half_rn(v0.y));
            *(__half2*)(g_A216 + (size_t)(m + 8) * HM + n) =
                __half2(__float2half_rn(v1.x), __float2half_rn(v1.y));
        }
    }
}

// ============================================================================
// GEMM2: single fp16 product + fused finish (round-12 version, unchanged).
// ============================================================================
#define NSTAGE 3
#define G2_TM 64
#define G2_NCHUNK 20
#define G2_SA (G2_TM * 128)     // 8192
#define G2_SB (NUP * 128)       // 18432
#define G2_STG (G2_SA + G2_SB)  // 26624
#define G2_SMEM (3 * G2_STG)    // 79872

__global__ __launch_bounds__(256, 1)
void gemm2_mma(const float* __restrict__ mem,
               const float* __restrict__ ba, const float* __restrict__ bb,
               const float* __restrict__ bva, const float* __restrict__ bvb,
               float* __restrict__ mem_new)
{
    extern __shared__ __align__(1024) unsigned char smem[];
    const uint32_t sbase = smem_u32(smem);
    const int tid = threadIdx.x;
    const int wid = tid >> 5;
    const int lid = tid & 31;
    const int M0 = blockIdx.x * G2_TM;

    const int prow = tid >> 3;
    const int pc   = tid & 7;
    const char* Ag = (const char*)g_A216 + (size_t)(M0 + prow) * (HM * 2) + pc * 16;
    const uint32_t sAoff = swz((uint32_t)prow * 128, (uint32_t)pc * 16);

    auto issue_load = [&](int kc, int stage) {
        const uint32_t cb = (uint32_t)kc * 128;
        const uint32_t sa  = sbase + stage * G2_STG;
        const uint32_t sbB = sa + G2_SA;
#pragma unroll
        for (int r = 0; r < 2; r++)
            CP_ASYNC16(sa + sAoff + r * 4096, Ag + cb + (size_t)r * (32 * HM * 2));
#pragma unroll
        for (int r = 0; r < 5; r++) {
            const int idx = tid + 256 * r;
            if (idx < NUP * 8) {
                const int row = idx >> 3, c = idx & 7;
                CP_ASYNC16(sbB + swz((uint32_t)row * 128, (uint32_t)c * 16),
                           (const char*)g_W216 + (size_t)row * (HM * 2) + c * 16 + cb);
            }
        }
        CP_COMMIT();
    };

    const int wm = (wid & 3) * 16;
    const int wn = (wid >> 2) * 72;
    const uint32_t arow128 = (uint32_t)(wm + (lid & 15)) * 128;
    const uint32_t aq      = (uint32_t)((lid >> 4) * 16);
    const uint32_t brow128 = (uint32_t)((lid & 7) + ((lid >> 4) & 1) * 8) * 128;
    const uint32_t bq      = (uint32_t)(((lid >> 3) & 1) * 16);
    const uint32_t brow2   = (uint32_t)(lid & 7) * 128;

    float acc[9][4];
#pragma unroll
    for (int j = 0; j < 9; j++)
#pragma unroll
        for (int q = 0; q < 4; q++) acc[j][q] = 0.f;

    issue_load(0, 0);
    issue_load(1, 1);

#pragma unroll 1
    for (int kc = 0; kc < G2_NCHUNK; kc++) {
        CP_WAIT1();
        __syncthreads();
        if (kc + 2 < G2_NCHUNK) issue_load(kc + 2, (kc + 2) % NSTAGE);
        else CP_COMMIT();

        const uint32_t sa  = sbase + (kc % NSTAGE) * G2_STG;
        const uint32_t sbB = sa + G2_SA;
#pragma unroll
        for (int kk = 0; kk < 4; kk++) {
            const uint32_t kb = (uint32_t)kk * 32;
            uint32_t A[4];
            ldsm_x4(A, sa + swz(arow128, kb + aq));
            uint32_t Bf[4][4], Bt[2];
#pragma unroll
            for (int nt = 0; nt < 4; nt++)
                ldsm_x4(Bf[nt], sbB + swz(brow128 + (wn + nt * 16) * 128, kb + bq));
            ldsm_x2(Bt, sbB + swz(brow2 + (wn + 64) * 128, kb + bq));
#pragma unroll
            for (int nt = 0; nt < 4; nt++) {
                mma_f16(acc[2 * nt],     A, Bf[nt][0], Bf[nt][1]);
                mma_f16(acc[2 * nt + 1], A, Bf[nt][2], Bf[nt][3]);
            }
            mma_f16(acc[8], A, Bt[0], Bt[1]);
        }
    }

    __syncthreads();
    float* su = (float*)smem;                      // [64][144]
    float* Pa = (float*)(smem + 64 * NUP * 4);     // [64][8]
    float* Pb = Pa + 64 * 8;
    {
        const int r0 = wm + (lid >> 2);
        const int r1 = r0 + 8;
#pragma unroll
        for (int nt = 0; nt < 9; nt++) {
            const int n = wn + nt * 8 + (lid & 3) * 2;
            float b0 = 0.f, b1 = 0.f;
            if (n < NU)     b0 = u_bias(n,     ba, bb, bva, bvb);
            if (n + 1 < NU) b1 = u_bias(n + 1, ba, bb, bva, bvb);
            su[r0 * NUP + n]     = acc[nt][0] + b0;
            su[r0 * NUP + n + 1] = acc[nt][1] + b1;
            su[r1 * NUP + n]     = acc[nt][2] + b0;
            su[r1 * NUP + n + 1] = acc[nt][3] + b1;
        }
    }
    __syncthreads();

    if (tid < 64) {
        const float* u   = su + tid * NUP;
        const float* al  = u;
        const float* be  = u + 4;
        const float* u0a = u + 8;
        const float* u1a = u + 40;
        const float* u0b = u + 72;
        const float* u1b = u + 104;

        float S1a = 0.f, S1b = 0.f;
#pragma unroll
        for (int j = 0; j < 32; j++) {
            const float xa = u1a[j], xa2 = xa * xa;
            const float xb = u1b[j], xb2 = xb * xb;
            S1a += xa2 * xa2 * fabsf(xa);
            S1b += xb2 * xb2 * fabsf(xb);
        }
        float ca[4], cb[4];
#pragma unroll
        for (int k = 0; k < 4; k++) {
            float S0a = 0.f, S0b = 0.f;
#pragma unroll
            for (int i = 0; i < 8; i++) {
                const float xa = u0a[8 * k + i], xa2 = xa * xa;
                const float xb = u0b[8 * k + i], xb2 = xb * xb;
                S0a += xa2 * xa2 * fabsf(xa);
                S0b += xb2 * xb2 * fabsf(xb);
            }
            const float na = fmaxf(exp2f(0.2f * log2f(S0a * S1a)), 1e-12f);
            const float nb = fmaxf(exp2f(0.2f * log2f(S0b * S1b)), 1e-12f);
            ca[k] = al[k] / na;
            cb[k] = be[k] / nb;
        }
#pragma unroll
        for (int ii = 0; ii < 8; ii++) {
            float pa = 0.f, pb = 0.f;
#pragma unroll
            for (int k = 0; k < 4; k++) {
                pa += ca[k] * u0a[8 * k + ii];
                pb += cb[k] * u0b[8 * k + ii];
            }
            Pa[tid * 8 + ii] = pa;
            Pb[tid * 8 + ii] = pb;
        }
    }
    __syncthreads();

#pragma unroll
    for (int e = 0; e < 64; e++) {
        const int idx = tid + e * 256;
        const int m = idx >> 8;
        const int c = idx & 255;
        const int ii = c >> 5;
        const int j  = c & 31;
        const float* u = su + m * NUP;
        mem_new[(size_t)(M0 + m) * MEMSZ + c] =
            mem[(size_t)(M0 + m) * MEMSZ + c] +
            0.25f * (u[40 + j] * Pa[m * 8 + ii] - u[104 + j] * Pb[m * 8 + ii]);
    }
}

// ============================================================================
// Launch
// ============================================================================
extern "C" void kernel_launch(void* const* d_in, const int* in_sizes, int n_in,
                              void* d_out, int out_size)
{
    const float* x   = (const float*)d_in[0];
    const float* h0  = (const float*)d_in[1];
    const float* mem = (const float*)d_in[2];
    const float* Wh  = (const float*)d_in[3];
    const float* bh  = (const float*)d_in[4];
    const float* Wa  = (const float*)d_in[5];
    const float* ba  = (const float*)d_in[6];
    const float* Wb  = (const float*)d_in[7];
    const float* bb  = (const float*)d_in[8];
    const float* Wva = (const float*)d_in[9];
    const float* bva = (const float*)d_in[10];
    const float* Wvb = (const float*)d_in[11];
    const float* bvb = (const float*)d_in[12];

    float* out     = (float*)d_out;
    float* mem_new = out;                              // [B, 256]
    float* h       = out + (size_t)B_ROWS * MEMSZ;     // [B, 1024]

    cudaFuncSetAttribute(gemm1_mma, cudaFuncAttributeMaxDynamicSharedMemorySize, G1_SMEM);
    cudaFuncSetAttribute(gemm2_mma, cudaFuncAttributeMaxDynamicSharedMemorySize, G2_SMEM);

    conv_all<<<NBLK_A + NBLK_W + NBLK_W2, 256>>>(x, h0, mem, Wh, Wa, Wb, Wva, Wvb);
    gemm1_mma<<<dim3(HID / G1_TN, B_ROWS / G1_TM), 128, G1_SMEM>>>(bh, h);
    gemm2_mma<<<B_ROWS / G2_TM, 256, G2_SMEM>>>(mem, ba, bb, bva, bvb, mem_new);
}